// round 7
// baseline (speedup 1.0000x reference)
#include <cuda_runtime.h>

// HierarchicalRouter: two-level MoE router.
//   x [16384,2048] f32; group_gate_w [8,2048]; expert_gate_w [64,2048]
// out = concat(valid_mask[16384,64] as f32, normalized_weights[16384,64])
//
// R4 (3rd retry; three GPU-broker timeouts, kernel never ran):
// fused GEMM (M=16384, N=72, K=2048), fp32x2 FFMA packed over K.
//  - coalesced x loads (4x16B per row, 8 rows/warp-LDG -> nL=8 not 32)
//  - x staged in smem as k-pairs, read via one conflict-free LDS.64/kk
//  - weights as LDS.128 broadcasts
//  - thread tile 1 token x 36 experts (36 indep FFMA2 chains)
//  - single __syncthreads per mainloop iteration

#define N_TOKENS 16384
#define DIM      2048
#define BM       128
#define BK       16
#define BKK      8
#define NITER    (DIM / BK)     // 128
#define THREADS  256
#define LSTRIDE  73

typedef unsigned long long u64;

__device__ __forceinline__ void ffma2(u64& acc, u64 a, u64 b) {
    asm("fma.rn.f32x2 %0, %1, %2, %0;" : "+l"(acc) : "l"(a), "l"(b));
}

struct SmemTiles {
    u64 xs[2][BKK][BM];   // x k-pairs: [buf][kk][token]      16 KB
    u64 ws[2][BKK][72];   // w k-pairs: [buf][kk][expert]      9 KB
};

__global__ __launch_bounds__(THREADS, 1)
void router_kernel(const float* __restrict__ x,
                   const float* __restrict__ ggw,
                   const float* __restrict__ egw,
                   float* __restrict__ out)
{
    __shared__ union {
        SmemTiles t;
        float logits[BM * LSTRIDE];   // reused after mainloop (37.4 KB)
    } sm;

    const int tid   = threadIdx.x;
    const int lane  = tid & 31;
    const int wid   = tid >> 5;
    const int ehalf = wid & 1;          // expert half: e0 = 0 or 36
    const int e0    = ehalf * 36;
    const int ltok  = (wid >> 1) * 32 + lane;   // this thread's token
    const int tok0  = blockIdx.x * BM;

    // ---- x loader: chunk c = tid&3 (16B within row), rows r, r+64 ----
    const int xc = tid & 3;
    const int xr = tid >> 2;            // 0..63
    const float* xp0 = x + (size_t)(tok0 + xr)      * DIM + xc * 4;
    const float* xp1 = x + (size_t)(tok0 + xr + 64) * DIM + xc * 4;

    // ---- w loader: idx -> e = idx>>2 (0..71), q = idx&3 ----
    const int we0 = tid >> 2;
    const int wq0 = tid & 3;
    const float* wp0 = ((we0 < 8) ? (ggw + (size_t)we0 * DIM)
                                  : (egw + (size_t)(we0 - 8) * DIM)) + wq0 * 4;
    const int we1 = (tid + 256) >> 2;   // 64..71 (tid<32 only)
    const int wq1 = (tid + 256) & 3;
    const float* wp1 = egw + (size_t)(we1 - 8) * DIM + wq1 * 4;

    u64 acc[36];
#pragma unroll
    for (int j = 0; j < 36; j++) acc[j] = 0ull;

    ulonglong2 xa, xb;   // staged x (2 k-pairs each)
    float4 wa, wb;

    auto ldg_tile = [&](int it) {
        const int k0 = it * BK;
        xa = *reinterpret_cast<const ulonglong2*>(xp0 + k0);
        xb = *reinterpret_cast<const ulonglong2*>(xp1 + k0);
        wa = *reinterpret_cast<const float4*>(wp0 + k0);
        if (tid < 32) wb = *reinterpret_cast<const float4*>(wp1 + k0);
    };

    auto sts_tile = [&](int b) {
        sm.t.xs[b][xc * 2 + 0][xr]      = xa.x;
        sm.t.xs[b][xc * 2 + 1][xr]      = xa.y;
        sm.t.xs[b][xc * 2 + 0][xr + 64] = xb.x;
        sm.t.xs[b][xc * 2 + 1][xr + 64] = xb.y;
        *reinterpret_cast<float2*>(&sm.t.ws[b][wq0 * 2 + 0][we0]) =
            make_float2(wa.x, wa.y);
        *reinterpret_cast<float2*>(&sm.t.ws[b][wq0 * 2 + 1][we0]) =
            make_float2(wa.z, wa.w);
        if (tid < 32) {
            *reinterpret_cast<float2*>(&sm.t.ws[b][wq1 * 2 + 0][we1]) =
                make_float2(wb.x, wb.y);
            *reinterpret_cast<float2*>(&sm.t.ws[b][wq1 * 2 + 1][we1]) =
                make_float2(wb.z, wb.w);
        }
    };

    auto compute = [&](int b) {
#pragma unroll
        for (int kk = 0; kk < BKK; kk++) {
            const u64 xk = sm.t.xs[b][kk][ltok];       // LDS.64 conflict-free
            const u64* wr = &sm.t.ws[b][kk][e0];       // broadcast reads
#pragma unroll
            for (int j = 0; j < 36; j += 2) {
                ulonglong2 w2 = *reinterpret_cast<const ulonglong2*>(wr + j);
                ffma2(acc[j],     xk, w2.x);
                ffma2(acc[j + 1], xk, w2.y);
            }
        }
    };

    // ---- mainloop: double-buffered, ONE barrier per iteration ----
    ldg_tile(0);
    sts_tile(0);
    __syncthreads();
    int cur = 0;
#pragma unroll 2
    for (int it = 0; it < NITER; ++it) {
        if (it + 1 < NITER) ldg_tile(it + 1);
        compute(cur);
        if (it + 1 < NITER) sts_tile(cur ^ 1);
        __syncthreads();
        cur ^= 1;
    }

    // ---- stage logits: sum even/odd k halves ----
#pragma unroll
    for (int j = 0; j < 36; j++) {
        float2 p = *reinterpret_cast<float2*>(&acc[j]);
        sm.logits[ltok * LSTRIDE + e0 + j] = p.x + p.y;
    }
    __syncthreads();

    // ---- epilogue: one thread per token ----
    if (tid < BM) {
        float* L = &sm.logits[tid * LSTRIDE];  // [0..7] group, [8..71] expert

        float gl[8];
#pragma unroll
        for (int g = 0; g < 8; g++) gl[g] = L[g];
        float gmax = gl[0];
#pragma unroll
        for (int g = 1; g < 8; g++) gmax = fmaxf(gmax, gl[g]);
        float ge[8], gsum = 0.0f;
#pragma unroll
        for (int g = 0; g < 8; g++) { ge[g] = expf(gl[g] - gmax); gsum += ge[g]; }
        float gp[8];
#pragma unroll
        for (int g = 0; g < 8; g++) gp[g] = ge[g] / gsum;

        unsigned long long vmask = 0ull;
        float swsum = 0.0f;
#pragma unroll
        for (int g = 0; g < 8; g++) {
            const bool gm = (gp[g] >= 0.125f);
            float el[8];
#pragma unroll
            for (int e = 0; e < 8; e++) el[e] = L[8 + g * 8 + e];
            float emax = el[0];
#pragma unroll
            for (int e = 1; e < 8; e++) emax = fmaxf(emax, el[e]);
            float ee[8], esum = 0.0f;
#pragma unroll
            for (int e = 0; e < 8; e++) { ee[e] = expf(el[e] - emax); esum += ee[e]; }
#pragma unroll
            for (int e = 0; e < 8; e++) {
                const float ep = ee[e] / esum;
                const bool val = gm && (ep >= 0.125f);
                const float sw = val ? gp[g] * ep : 0.0f;
                swsum += sw;
                L[8 + g * 8 + e] = sw;
                if (val) vmask |= (1ull << (g * 8 + e));
            }
        }
        swsum = fmaxf(swsum, 1e-9f);
        const float inv = 1.0f / swsum;

        const int gt = tok0 + tid;
        float* om = out + (size_t)gt * 64;
        float* ow = out + (size_t)N_TOKENS * 64 + (size_t)gt * 64;
#pragma unroll
        for (int i = 0; i < 64; i += 4) {
            float4 m4, w4;
            m4.x = ((vmask >> (i + 0)) & 1ull) ? 1.0f : 0.0f;
            m4.y = ((vmask >> (i + 1)) & 1ull) ? 1.0f : 0.0f;
            m4.z = ((vmask >> (i + 2)) & 1ull) ? 1.0f : 0.0f;
            m4.w = ((vmask >> (i + 3)) & 1ull) ? 1.0f : 0.0f;
            w4.x = L[8 + i + 0] * inv;
            w4.y = L[8 + i + 1] * inv;
            w4.z = L[8 + i + 2] * inv;
            w4.w = L[8 + i + 3] * inv;
            *reinterpret_cast<float4*>(om + i) = m4;
            *reinterpret_cast<float4*>(ow + i) = w4;
        }
    }
}

extern "C" void kernel_launch(void* const* d_in, const int* in_sizes, int n_in,
                              void* d_out, int out_size) {
    const float* x   = (const float*)d_in[0];
    const float* ggw = (const float*)d_in[1];
    const float* egw = (const float*)d_in[2];
    float* out = (float*)d_out;

    const int tokens = in_sizes[0] / DIM;   // 16384
    const int grid = tokens / BM;           // 128
    router_kernel<<<grid, THREADS>>>(x, ggw, egw, out);
}

// round 10
// speedup vs baseline: 1.6272x; 1.6272x over previous
#include <cuda_runtime.h>

// HierarchicalRouter: two-level MoE router.
//   x [16384,2048] f32; group_gate_w [8,2048]; expert_gate_w [64,2048]
// out = concat(valid_mask[16384,64] as f32, normalized_weights[16384,64])
//
// R5 (2nd retry; broker timeouts, never ran): 4-deep software pipeline
// (2 smem stages + 2 register stages, LDG issued 2 iterations ahead, STS
// consumes data LDG'd a full iteration earlier) to hide DRAM latency from
// the per-iteration barrier.
// Compute tile: 4 tokens (strided) x 9 experts per thread, k-pair FFMA2.

#define N_TOKENS 16384
#define DIM      2048
#define BM       128
#define BK       16
#define BKK      8
#define NITER    (DIM / BK)     // 128
#define THREADS  256
#define LSTRIDE  73
#define XROW     130            // padded token row (u64) -> conflict-free STS
#define WGP      10             // padded u64 per expert group (16B-aligned)

typedef unsigned long long u64;

__device__ __forceinline__ void ffma2(u64& acc, u64 a, u64 b) {
    asm("fma.rn.f32x2 %0, %1, %2, %0;" : "+l"(acc) : "l"(a), "l"(b));
}

struct Stage {            // register-staged gmem data for one tile
    ulonglong2 xa, xb;    // 2 k-pair pairs for rows xr, xr+64
    float4 wa, wb;        // weight quads (wb only tid<32)
};

__global__ __launch_bounds__(THREADS, 1)
void router_kernel(const float* __restrict__ x,
                   const float* __restrict__ ggw,
                   const float* __restrict__ egw,
                   float* __restrict__ out)
{
    __shared__ __align__(16) union {
        struct {
            u64 xs[2][BKK][XROW];   // x k-pairs [buf][kk][token]  16.6 KB
            u64 ws[2][BKK][8 * WGP];// w k-pairs [buf][kk][group*10+j] 10 KB
        } t;
        float logits[BM * LSTRIDE]; // reused after mainloop (37.4 KB)
    } sm;

    const int tid  = threadIdx.x;
    const int tg   = tid & 31;         // lane
    const int wid  = tid >> 5;         // expert group 0..7
    const int e0   = wid * 9;          // first output index of this group
    const int tok0 = blockIdx.x * BM;

    // ---- x loader: chunk xc = tid&3 (16B), rows xr and xr+64 ----
    const int xc = tid & 3;
    const int xr = tid >> 2;           // 0..63
    const float* xp0 = x + (size_t)(tok0 + xr)      * DIM + xc * 4;
    const float* xp1 = x + (size_t)(tok0 + xr + 64) * DIM + xc * 4;

    // ---- w loader: idx -> e = idx>>2 (0..71), q = idx&3 ----
    const int we0 = tid >> 2;
    const int wq0 = tid & 3;
    const float* wp0 = ((we0 < 8) ? (ggw + (size_t)we0 * DIM)
                                  : (egw + (size_t)(we0 - 8) * DIM)) + wq0 * 4;
    const int wd0 = (we0 / 9) * WGP + (we0 % 9);
    const int we1 = (tid + 256) >> 2;  // 64..71 (tid<32 only)
    const int wq1 = (tid + 256) & 3;
    const float* wp1 = egw + (size_t)(we1 - 8) * DIM + wq1 * 4;
    const int wd1 = (we1 / 9) * WGP + (we1 % 9);

    u64 acc[4][9];
#pragma unroll
    for (int m = 0; m < 4; m++)
#pragma unroll
        for (int j = 0; j < 9; j++) acc[m][j] = 0ull;

    auto ldg_tile = [&](int it, Stage& s) {
        const int k0 = it * BK;
        s.xa = *reinterpret_cast<const ulonglong2*>(xp0 + k0);
        s.xb = *reinterpret_cast<const ulonglong2*>(xp1 + k0);
        s.wa = *reinterpret_cast<const float4*>(wp0 + k0);
        if (tid < 32) s.wb = *reinterpret_cast<const float4*>(wp1 + k0);
    };

    auto sts_tile = [&](int b, const Stage& s) {
        sm.t.xs[b][xc * 2 + 0][xr]      = s.xa.x;
        sm.t.xs[b][xc * 2 + 1][xr]      = s.xa.y;
        sm.t.xs[b][xc * 2 + 0][xr + 64] = s.xb.x;
        sm.t.xs[b][xc * 2 + 1][xr + 64] = s.xb.y;
        *reinterpret_cast<float2*>(&sm.t.ws[b][wq0 * 2 + 0][wd0]) =
            make_float2(s.wa.x, s.wa.y);
        *reinterpret_cast<float2*>(&sm.t.ws[b][wq0 * 2 + 1][wd0]) =
            make_float2(s.wa.z, s.wa.w);
        if (tid < 32) {
            *reinterpret_cast<float2*>(&sm.t.ws[b][wq1 * 2 + 0][wd1]) =
                make_float2(s.wb.x, s.wb.y);
            *reinterpret_cast<float2*>(&sm.t.ws[b][wq1 * 2 + 1][wd1]) =
                make_float2(s.wb.z, s.wb.w);
        }
    };

    auto compute = [&](int b) {
#pragma unroll
        for (int kk = 0; kk < BKK; kk++) {
            // 4 strided tokens: conflict-free LDS.64 each
            const u64 x0 = sm.t.xs[b][kk][tg];
            const u64 x1 = sm.t.xs[b][kk][tg + 32];
            const u64 x2 = sm.t.xs[b][kk][tg + 64];
            const u64 x3 = sm.t.xs[b][kk][tg + 96];
            // 9 expert k-pairs: aligned broadcast loads
            const u64* wr = &sm.t.ws[b][kk][wid * WGP];
            const ulonglong2 w01 = *reinterpret_cast<const ulonglong2*>(wr + 0);
            const ulonglong2 w23 = *reinterpret_cast<const ulonglong2*>(wr + 2);
            const ulonglong2 w45 = *reinterpret_cast<const ulonglong2*>(wr + 4);
            const ulonglong2 w67 = *reinterpret_cast<const ulonglong2*>(wr + 6);
            const u64 w8 = wr[8];

            ffma2(acc[0][0], x0, w01.x); ffma2(acc[1][0], x1, w01.x);
            ffma2(acc[2][0], x2, w01.x); ffma2(acc[3][0], x3, w01.x);
            ffma2(acc[0][1], x0, w01.y); ffma2(acc[1][1], x1, w01.y);
            ffma2(acc[2][1], x2, w01.y); ffma2(acc[3][1], x3, w01.y);
            ffma2(acc[0][2], x0, w23.x); ffma2(acc[1][2], x1, w23.x);
            ffma2(acc[2][2], x2, w23.x); ffma2(acc[3][2], x3, w23.x);
            ffma2(acc[0][3], x0, w23.y); ffma2(acc[1][3], x1, w23.y);
            ffma2(acc[2][3], x2, w23.y); ffma2(acc[3][3], x3, w23.y);
            ffma2(acc[0][4], x0, w45.x); ffma2(acc[1][4], x1, w45.x);
            ffma2(acc[2][4], x2, w45.x); ffma2(acc[3][4], x3, w45.x);
            ffma2(acc[0][5], x0, w45.y); ffma2(acc[1][5], x1, w45.y);
            ffma2(acc[2][5], x2, w45.y); ffma2(acc[3][5], x3, w45.y);
            ffma2(acc[0][6], x0, w67.x); ffma2(acc[1][6], x1, w67.x);
            ffma2(acc[2][6], x2, w67.x); ffma2(acc[3][6], x3, w67.x);
            ffma2(acc[0][7], x0, w67.y); ffma2(acc[1][7], x1, w67.y);
            ffma2(acc[2][7], x2, w67.y); ffma2(acc[3][7], x3, w67.y);
            ffma2(acc[0][8], x0, w8);    ffma2(acc[1][8], x1, w8);
            ffma2(acc[2][8], x2, w8);    ffma2(acc[3][8], x3, w8);
        }
    };

    // ---- 4-deep pipeline: 2 reg stages + 2 smem stages ----
    Stage P, Q;
    ldg_tile(0, P);
    ldg_tile(1, Q);
    sts_tile(0, P);
    __syncthreads();

    int cur = 0;
#pragma unroll 1
    for (int it = 0; it < NITER; it += 2) {
        // iter it: P free -> prefetch it+2; Q holds tile it+1
        if (it + 2 < NITER) ldg_tile(it + 2, P);
        compute(cur);
        if (it + 1 < NITER) sts_tile(cur ^ 1, Q);
        __syncthreads();
        cur ^= 1;
        // iter it+1: Q free -> prefetch it+3; P holds tile it+2
        if (it + 3 < NITER) ldg_tile(it + 3, Q);
        compute(cur);
        if (it + 2 < NITER) sts_tile(cur ^ 1, P);
        __syncthreads();
        cur ^= 1;
    }

    // ---- stage logits: sum even/odd k halves ----
#pragma unroll
    for (int m = 0; m < 4; m++) {
        const int tok = tg + 32 * m;
#pragma unroll
        for (int j = 0; j < 9; j++) {
            float2 p = *reinterpret_cast<float2*>(&acc[m][j]);
            sm.logits[tok * LSTRIDE + e0 + j] = p.x + p.y;
        }
    }
    __syncthreads();

    // ---- epilogue: one thread per token ----
    if (tid < BM) {
        float* L = &sm.logits[tid * LSTRIDE];  // [0..7] group, [8..71] expert

        float gl[8];
#pragma unroll
        for (int g = 0; g < 8; g++) gl[g] = L[g];
        float gmax = gl[0];
#pragma unroll
        for (int g = 1; g < 8; g++) gmax = fmaxf(gmax, gl[g]);
        float ge[8], gsum = 0.0f;
#pragma unroll
        for (int g = 0; g < 8; g++) { ge[g] = expf(gl[g] - gmax); gsum += ge[g]; }
        float gp[8];
#pragma unroll
        for (int g = 0; g < 8; g++) gp[g] = ge[g] / gsum;

        unsigned long long vmask = 0ull;
        float swsum = 0.0f;
#pragma unroll
        for (int g = 0; g < 8; g++) {
            const bool gm = (gp[g] >= 0.125f);
            float el[8];
#pragma unroll
            for (int e = 0; e < 8; e++) el[e] = L[8 + g * 8 + e];
            float emax = el[0];
#pragma unroll
            for (int e = 1; e < 8; e++) emax = fmaxf(emax, el[e]);
            float ee[8], esum = 0.0f;
#pragma unroll
            for (int e = 0; e < 8; e++) { ee[e] = expf(el[e] - emax); esum += ee[e]; }
#pragma unroll
            for (int e = 0; e < 8; e++) {
                const float ep = ee[e] / esum;
                const bool val = gm && (ep >= 0.125f);
                const float sw = val ? gp[g] * ep : 0.0f;
                swsum += sw;
                L[8 + g * 8 + e] = sw;
                if (val) vmask |= (1ull << (g * 8 + e));
            }
        }
        swsum = fmaxf(swsum, 1e-9f);
        const float inv = 1.0f / swsum;

        const int gt = tok0 + tid;
        float* om = out + (size_t)gt * 64;
        float* ow = out + (size_t)N_TOKENS * 64 + (size_t)gt * 64;
#pragma unroll
        for (int i = 0; i < 64; i += 4) {
            float4 m4, w4;
            m4.x = ((vmask >> (i + 0)) & 1ull) ? 1.0f : 0.0f;
            m4.y = ((vmask >> (i + 1)) & 1ull) ? 1.0f : 0.0f;
            m4.z = ((vmask >> (i + 2)) & 1ull) ? 1.0f : 0.0f;
            m4.w = ((vmask >> (i + 3)) & 1ull) ? 1.0f : 0.0f;
            w4.x = L[8 + i + 0] * inv;
            w4.y = L[8 + i + 1] * inv;
            w4.z = L[8 + i + 2] * inv;
            w4.w = L[8 + i + 3] * inv;
            *reinterpret_cast<float4*>(om + i) = m4;
            *reinterpret_cast<float4*>(ow + i) = w4;
        }
    }
}

extern "C" void kernel_launch(void* const* d_in, const int* in_sizes, int n_in,
                              void* d_out, int out_size) {
    const float* x   = (const float*)d_in[0];
    const float* ggw = (const float*)d_in[1];
    const float* egw = (const float*)d_in[2];
    float* out = (float*)d_out;

    const int tokens = in_sizes[0] / DIM;   // 16384
    const int grid = tokens / BM;           // 128
    router_kernel<<<grid, THREADS>>>(x, ggw, egw, out);
}